// round 9
// baseline (speedup 1.0000x reference)
#include <cuda_runtime.h>

// PolynomialADMRSolver — B=4096, N=32, D=1024, fp32.
// out[b,d] = mean_k( x^e_k ), e={2,3,5,7}, x = states[b,d]*(sum_n w[b,n]*nb[b,n,d] + valence[b])
//
// R9: quarter-row CTAs — 64 threads, grid = 16384 (4 CTAs per row).
// R8 confirmed finer CTA retirement quanta raise time-averaged DRAM queue
// depth (86.4 -> 87.7% DRAM-active); halve the quantum again. Same 24
// warps/SM (12 CTAs x 2 warps at 80 regs), batch-16 front-loaded reads.

static constexpr int B = 4096;
static constexpr int N = 32;
static constexpr int D = 1024;
static constexpr int THREADS = 64;             // quarter-row: 64 float4 lanes
static constexpr int SPLIT = 4;                // CTAs per row
static constexpr int BATCH = 16;
static constexpr int GRID = B * SPLIT;         // 16384

__global__ __launch_bounds__(THREADS, 12)      // ~85 regs/thread budget
void poly_admr_kernel(const float* __restrict__ states,
                      const float* __restrict__ neighbor_states,
                      const float* __restrict__ adjacency_weight,
                      const float* __restrict__ valence,
                      float* __restrict__ out)
{
    const int b    = blockIdx.x >> 2;            // row
    const int part = blockIdx.x & 3;             // which quarter of D
    const int t    = (part << 6) + threadIdx.x;  // float4 lane in [0,256)

    const float4* __restrict__ nb = reinterpret_cast<const float4*>(
        neighbor_states + (size_t)b * N * D);
    const float* __restrict__ wrow = adjacency_weight + (size_t)b * N;

    // Hoisted: latencies overlap the neighbor stream.
    const float v = __ldg(&valence[b]);
    const float4 s = reinterpret_cast<const float4*>(states + (size_t)b * D)[t];

    float4 acc = make_float4(0.f, 0.f, 0.f, 0.f);

    #pragma unroll
    for (int n0 = 0; n0 < N; n0 += BATCH) {
        float4 x[BATCH];
        #pragma unroll
        for (int i = 0; i < BATCH; ++i)
            x[i] = nb[(size_t)(n0 + i) * (D / 4) + t];

        #pragma unroll
        for (int i = 0; i < BATCH; ++i) {
            const float wn = __ldg(&wrow[n0 + i]);   // warp-uniform, L1-hit
            acc.x = fmaf(wn, x[i].x, acc.x);
            acc.y = fmaf(wn, x[i].y, acc.y);
            acc.z = fmaf(wn, x[i].z, acc.z);
            acc.w = fmaf(wn, x[i].w, acc.w);
        }
    }

    float4 r;
    {
        float x = s.x * (acc.x + v);
        float x2 = x * x, x3 = x2 * x, x5 = x3 * x2, x7 = x5 * x2;
        r.x = 0.25f * (x2 + x3 + x5 + x7);
    }
    {
        float x = s.y * (acc.y + v);
        float x2 = x * x, x3 = x2 * x, x5 = x3 * x2, x7 = x5 * x2;
        r.y = 0.25f * (x2 + x3 + x5 + x7);
    }
    {
        float x = s.z * (acc.z + v);
        float x2 = x * x, x3 = x2 * x, x5 = x3 * x2, x7 = x5 * x2;
        r.z = 0.25f * (x2 + x3 + x5 + x7);
    }
    {
        float x = s.w * (acc.w + v);
        float x2 = x * x, x3 = x2 * x, x5 = x3 * x2, x7 = x5 * x2;
        r.w = 0.25f * (x2 + x3 + x5 + x7);
    }

    reinterpret_cast<float4*>(out + (size_t)b * D)[t] = r;
}

extern "C" void kernel_launch(void* const* d_in, const int* in_sizes, int n_in,
                              void* d_out, int out_size)
{
    const float* states            = (const float*)d_in[0];
    const float* neighbor_states   = (const float*)d_in[1];
    const float* adjacency_weight  = (const float*)d_in[2];
    const float* valence           = (const float*)d_in[3];
    float* out = (float*)d_out;

    poly_admr_kernel<<<GRID, THREADS>>>(states, neighbor_states,
                                        adjacency_weight, valence, out);
}

// round 10
// speedup vs baseline: 1.0030x; 1.0030x over previous
#include <cuda_runtime.h>

// PolynomialADMRSolver — B=4096, N=32, D=1024, fp32.
// out[b,d] = mean_k( x^e_k ), e={2,3,5,7}, x = states[b,d]*(sum_n w[b,n]*nb[b,n,d] + valence[b])
//
// R10: R8 optimum (half-row CTAs, 128 thr, grid=8192, batch-16, 80 regs,
// 6 CTAs/SM) + __stcs streaming store on the output (keep dead write lines
// from displacing read sectors in L2). Granularity curve bracketed across
// R6/R8/R9: 128-thr CTAs are the optimum (DRAM 87.7%, 6.95 TB/s).

static constexpr int B = 4096;
static constexpr int N = 32;
static constexpr int D = 1024;
static constexpr int THREADS = 128;            // half-row: 128 float4 lanes
static constexpr int BATCH = 16;
static constexpr int GRID = B * 2;             // 8192

__global__ __launch_bounds__(THREADS, 6)       // ~85 regs/thread budget
void poly_admr_kernel(const float* __restrict__ states,
                      const float* __restrict__ neighbor_states,
                      const float* __restrict__ adjacency_weight,
                      const float* __restrict__ valence,
                      float* __restrict__ out)
{
    const int b    = blockIdx.x >> 1;            // row
    const int half = blockIdx.x & 1;             // which half of D
    const int t    = (half << 7) + threadIdx.x;  // float4 lane in [0,256)

    const float4* __restrict__ nb = reinterpret_cast<const float4*>(
        neighbor_states + (size_t)b * N * D);
    const float* __restrict__ wrow = adjacency_weight + (size_t)b * N;

    // Hoisted: latencies overlap the neighbor stream.
    const float v = __ldg(&valence[b]);
    const float4 s = reinterpret_cast<const float4*>(states + (size_t)b * D)[t];

    float4 acc = make_float4(0.f, 0.f, 0.f, 0.f);

    #pragma unroll
    for (int n0 = 0; n0 < N; n0 += BATCH) {
        float4 x[BATCH];
        #pragma unroll
        for (int i = 0; i < BATCH; ++i)
            x[i] = nb[(size_t)(n0 + i) * (D / 4) + t];

        #pragma unroll
        for (int i = 0; i < BATCH; ++i) {
            const float wn = __ldg(&wrow[n0 + i]);   // warp-uniform, L1-hit
            acc.x = fmaf(wn, x[i].x, acc.x);
            acc.y = fmaf(wn, x[i].y, acc.y);
            acc.z = fmaf(wn, x[i].z, acc.z);
            acc.w = fmaf(wn, x[i].w, acc.w);
        }
    }

    float4 r;
    {
        float x = s.x * (acc.x + v);
        float x2 = x * x, x3 = x2 * x, x5 = x3 * x2, x7 = x5 * x2;
        r.x = 0.25f * (x2 + x3 + x5 + x7);
    }
    {
        float x = s.y * (acc.y + v);
        float x2 = x * x, x3 = x2 * x, x5 = x3 * x2, x7 = x5 * x2;
        r.y = 0.25f * (x2 + x3 + x5 + x7);
    }
    {
        float x = s.z * (acc.z + v);
        float x2 = x * x, x3 = x2 * x, x5 = x3 * x2, x7 = x5 * x2;
        r.z = 0.25f * (x2 + x3 + x5 + x7);
    }
    {
        float x = s.w * (acc.w + v);
        float x2 = x * x, x3 = x2 * x, x5 = x3 * x2, x7 = x5 * x2;
        r.w = 0.25f * (x2 + x3 + x5 + x7);
    }

    // Streaming store: evict-first, output lines are dead after write.
    __stcs(&reinterpret_cast<float4*>(out + (size_t)b * D)[t], r);
}

extern "C" void kernel_launch(void* const* d_in, const int* in_sizes, int n_in,
                              void* d_out, int out_size)
{
    const float* states            = (const float*)d_in[0];
    const float* neighbor_states   = (const float*)d_in[1];
    const float* adjacency_weight  = (const float*)d_in[2];
    const float* valence           = (const float*)d_in[3];
    float* out = (float*)d_out;

    poly_admr_kernel<<<GRID, THREADS>>>(states, neighbor_states,
                                        adjacency_weight, valence, out);
}